// round 1
// baseline (speedup 1.0000x reference)
#include <cuda_runtime.h>

#define NN 100000
#define NE 1600000
#define FH 128
#define NG 256
#define NA 32

#define SCAN_BS 512
#define SCAN_NB ((NN + SCAN_BS - 1) / SCAN_BS)   // 196

// ---------------- scratch (device globals; no runtime allocation) ----------
__device__ float g_h[(size_t)NN * FH];     // h = X @ W (51.2 MB)
__device__ float g_t[(size_t)NN * FH];     // layer output (51.2 MB)
__device__ int   g_deg[NN];
__device__ float g_dinv[NN];
__device__ int   g_off[NN + 1];
__device__ int   g_cur[NN];
__device__ int   g_esrc[NE];
__device__ int   g_bsum[SCAN_NB];
__device__ float g_pool[NG * FH];
__device__ int   g_cnt[NG];

// ---------------- packed f32x2 helpers -------------------------------------
__device__ __forceinline__ void fma2(unsigned long long& d,
                                     unsigned long long a,
                                     unsigned long long b) {
    asm volatile("fma.rn.f32x2 %0, %1, %2, %0;" : "+l"(d) : "l"(a), "l"(b));
}
__device__ __forceinline__ unsigned long long packdup(float x) {
    unsigned long long d;
    asm("mov.b64 %0, {%1, %1};" : "=l"(d) : "r"(__float_as_uint(x)));
    return d;
}

// ---------------- small utility kernels ------------------------------------
__global__ void k_zero() {
    int i = blockIdx.x * blockDim.x + threadIdx.x;
    if (i < NN) g_deg[i] = 0;
    if (i < NG * FH) g_pool[i] = 0.f;
    if (i < NG) g_cnt[i] = 0;
}

__global__ void k_deg(const int* __restrict__ ei) {
    int e = blockIdx.x * blockDim.x + threadIdx.x;
    if (e < NE) atomicAdd(&g_deg[ei[NE + e]], 1);
}

__global__ void k_dinv() {
    int i = blockIdx.x * blockDim.x + threadIdx.x;
    if (i < NN) g_dinv[i] = rsqrtf((float)g_deg[i] + 1.0f);
}

__global__ void k_scan1() {
    __shared__ int s[SCAN_BS];
    int idx = blockIdx.x * SCAN_BS + threadIdx.x;
    int v = (idx < NN) ? g_deg[idx] : 0;
    s[threadIdx.x] = v;
    __syncthreads();
    for (int d = 1; d < SCAN_BS; d <<= 1) {
        int t = (threadIdx.x >= d) ? s[threadIdx.x - d] : 0;
        __syncthreads();
        s[threadIdx.x] += t;
        __syncthreads();
    }
    if (idx < NN) g_off[idx + 1] = s[threadIdx.x];
    if (threadIdx.x == SCAN_BS - 1) g_bsum[blockIdx.x] = s[SCAN_BS - 1];
}

__global__ void k_scan2() {
    __shared__ int s[256];
    int v = (threadIdx.x < SCAN_NB) ? g_bsum[threadIdx.x] : 0;
    s[threadIdx.x] = v;
    __syncthreads();
    for (int d = 1; d < 256; d <<= 1) {
        int t = (threadIdx.x >= d) ? s[threadIdx.x - d] : 0;
        __syncthreads();
        s[threadIdx.x] += t;
        __syncthreads();
    }
    if (threadIdx.x < SCAN_NB) g_bsum[threadIdx.x] = s[threadIdx.x];
}

__global__ void k_scan3() {
    int idx = blockIdx.x * SCAN_BS + threadIdx.x;
    int base = (blockIdx.x == 0) ? 0 : g_bsum[blockIdx.x - 1];
    if (idx < NN) g_off[idx + 1] += base;
    if (idx == 0) g_off[0] = 0;
}

__global__ void k_cur() {
    int i = blockIdx.x * blockDim.x + threadIdx.x;
    if (i < NN) g_cur[i] = g_off[i];
}

__global__ void k_fill(const int* __restrict__ ei) {
    int e = blockIdx.x * blockDim.x + threadIdx.x;
    if (e < NE) {
        int src = ei[e];
        int dst = ei[NE + e];
        int p = atomicAdd(&g_cur[dst], 1);
        g_esrc[p] = src;
    }
}

// ---------------- GEMM: Y[nrows,128] = X[nrows,128] @ W[128,128] ------------
// 256 threads/block, 64 rows x 128 cols per block, f32x2 packed FMA.
__global__ void k_gemm(const float* __restrict__ X, const float* __restrict__ W,
                       float* __restrict__ Y, int nrows) {
    extern __shared__ float sm[];
    float* Ws = sm;                // 128*128 floats (64KB)
    float* Xs = sm + FH * FH;      // 64*128 floats (32KB)
    int tid = threadIdx.x;
    int row0 = blockIdx.x * 64;

    const float4* W4 = (const float4*)W;
    float4* Ws4 = (float4*)Ws;
#pragma unroll
    for (int i = 0; i < 16; i++) Ws4[tid + 256 * i] = W4[tid + 256 * i];

    const float4* X4 = (const float4*)X;
    float4* Xs4 = (float4*)Xs;
#pragma unroll
    for (int i = 0; i < 8; i++) {
        int idx = tid + 256 * i;           // < 2048
        int r = idx >> 5;
        float4 v = make_float4(0.f, 0.f, 0.f, 0.f);
        if (row0 + r < nrows) v = X4[(size_t)(row0 + r) * 32 + (idx & 31)];
        Xs4[idx] = v;
    }
    __syncthreads();

    int cx = tid & 15;   // col group: cols 8*cx .. 8*cx+7
    int cy = tid >> 4;   // rows cy, cy+16, cy+32, cy+48
    unsigned long long acc[4][4];
#pragma unroll
    for (int i = 0; i < 4; i++)
#pragma unroll
        for (int j = 0; j < 4; j++) acc[i][j] = 0ull;

#pragma unroll 8
    for (int k = 0; k < FH; k++) {
        const ulonglong2* wp = (const ulonglong2*)&Ws[k * FH + cx * 8];
        ulonglong2 wa = wp[0];
        ulonglong2 wb = wp[1];
#pragma unroll
        for (int i = 0; i < 4; i++) {
            unsigned long long xd = packdup(Xs[(cy + 16 * i) * FH + k]);
            fma2(acc[i][0], xd, wa.x);
            fma2(acc[i][1], xd, wa.y);
            fma2(acc[i][2], xd, wb.x);
            fma2(acc[i][3], xd, wb.y);
        }
    }
#pragma unroll
    for (int i = 0; i < 4; i++) {
        int r = row0 + cy + 16 * i;
        if (r < nrows) {
            ulonglong2* yp = (ulonglong2*)&Y[(size_t)r * FH + cx * 8];
            ulonglong2 a; a.x = acc[i][0]; a.y = acc[i][1];
            ulonglong2 b; b.x = acc[i][2]; b.y = acc[i][3];
            yp[0] = a;
            yp[1] = b;
        }
    }
}

// ---------------- aggregation: one warp per dst node ------------------------
// out[dst] = relu( dinv[dst]*sum_{src} dinv[src]*H[src] + dinv[dst]^2*H[dst] + b )
// Optionally fuses graph mean-pool accumulation (layer 2).
__global__ void k_agg(const float* __restrict__ H, const float* __restrict__ bias,
                      const int* __restrict__ batch, float* __restrict__ Out,
                      int do_pool) {
    int node = (blockIdx.x * blockDim.x + threadIdx.x) >> 5;
    int lane = threadIdx.x & 31;
    if (node >= NN) return;
    int s = g_off[node];
    int e = g_off[node + 1];
    const float4* H4 = (const float4*)H;
    float ax = 0.f, ay = 0.f, az = 0.f, aw = 0.f;
#pragma unroll 4
    for (int j = s; j < e; j++) {
        int src = __ldg(&g_esrc[j]);
        float c = __ldg(&g_dinv[src]);
        float4 hv = __ldg(&H4[(size_t)src * 32 + lane]);
        ax += c * hv.x; ay += c * hv.y; az += c * hv.z; aw += c * hv.w;
    }
    float di = g_dinv[node];
    float d2 = di * di;
    float4 hs = __ldg(&H4[(size_t)node * 32 + lane]);
    float4 bv = __ldg(&((const float4*)bias)[lane]);
    float rx = fmaxf(di * ax + d2 * hs.x + bv.x, 0.f);
    float ry = fmaxf(di * ay + d2 * hs.y + bv.y, 0.f);
    float rz = fmaxf(di * az + d2 * hs.z + bv.z, 0.f);
    float rw = fmaxf(di * aw + d2 * hs.w + bv.w, 0.f);
    if (Out) {
        float4 o; o.x = rx; o.y = ry; o.z = rz; o.w = rw;
        ((float4*)Out)[(size_t)node * 32 + lane] = o;
    }
    if (do_pool) {
        int b = __ldg(&batch[node]);
        float* p = &g_pool[b * FH + lane * 4];
        atomicAdd(p + 0, rx);
        atomicAdd(p + 1, ry);
        atomicAdd(p + 2, rz);
        atomicAdd(p + 3, rw);
        if (lane == 0) atomicAdd(&g_cnt[b], 1);
    }
}

// ---------------- final MLP head: one block per graph -----------------------
__global__ void k_mlp(const float* __restrict__ Wl1, const float* __restrict__ bl1,
                      const float* __restrict__ Wl2, const float* __restrict__ bl2,
                      float* __restrict__ out) {
    __shared__ float gv[FH];
    __shared__ float tv[FH];
    int b = blockIdx.x, tid = threadIdx.x;
    float c = fmaxf((float)g_cnt[b], 1.0f);
    gv[tid] = g_pool[b * FH + tid] / c;
    __syncthreads();
    float s = bl1[tid];
#pragma unroll 8
    for (int k = 0; k < FH; k++) s += gv[k] * Wl1[k * FH + tid];
    tv[tid] = fmaxf(s, 0.f);
    __syncthreads();
    if (tid < NA) {
        float o = bl2[tid];
#pragma unroll 8
        for (int k = 0; k < FH; k++) o += tv[k] * Wl2[k * NA + tid];
        out[b * NA + tid] = o;
    }
}

// ---------------- launch ----------------------------------------------------
extern "C" void kernel_launch(void* const* d_in, const int* in_sizes, int n_in,
                              void* d_out, int out_size) {
    const float* x   = (const float*)d_in[0];
    const int*   ei  = (const int*)d_in[1];
    const int*   bat = (const int*)d_in[2];
    const float* W1  = (const float*)d_in[3];
    const float* b1  = (const float*)d_in[4];
    const float* W2  = (const float*)d_in[5];
    const float* b2  = (const float*)d_in[6];
    const float* Wl1 = (const float*)d_in[7];
    const float* bl1 = (const float*)d_in[8];
    const float* Wl2 = (const float*)d_in[9];
    const float* bl2 = (const float*)d_in[10];
    float* out = (float*)d_out;

    float *ph = nullptr, *pt = nullptr;
    cudaGetSymbolAddress((void**)&ph, g_h);
    cudaGetSymbolAddress((void**)&pt, g_t);

    const int SMEM = (FH * FH + 64 * FH) * sizeof(float);   // 96 KB
    cudaFuncSetAttribute(k_gemm, cudaFuncAttributeMaxDynamicSharedMemorySize, SMEM);

    // degree + normalization + CSR build
    k_zero<<<(NN + 255) / 256, 256>>>();
    k_deg<<<(NE + 255) / 256, 256>>>(ei);
    k_dinv<<<(NN + 255) / 256, 256>>>();
    k_scan1<<<SCAN_NB, SCAN_BS>>>();
    k_scan2<<<1, 256>>>();
    k_scan3<<<SCAN_NB, SCAN_BS>>>();
    k_cur<<<(NN + 255) / 256, 256>>>();
    k_fill<<<(NE + 255) / 256, 256>>>(ei);

    // layer 1: h = x@W1 ; t = relu(agg(h) + self + b1)
    k_gemm<<<(NN + 63) / 64, 256, SMEM>>>(x, W1, ph, NN);
    k_agg<<<(NN * 32 + 255) / 256, 256>>>(ph, b1, bat, pt, 0);

    // layer 2: h = t@W2 ; fused agg + relu + mean-pool accumulation
    k_gemm<<<(NN + 63) / 64, 256, SMEM>>>(pt, W2, ph, NN);
    k_agg<<<(NN * 32 + 255) / 256, 256>>>(ph, b2, bat, nullptr, 1);

    // head
    k_mlp<<<NG, FH>>>(Wl1, bl1, Wl2, bl2, out);
}

// round 3
// speedup vs baseline: 1.8972x; 1.8972x over previous
#include <cuda_runtime.h>
#include <cuda_fp16.h>
#include <cstdint>

#define NN 100000
#define NE 1600000
#define FH 128
#define NG 256
#define NA 32

#define SCAN_BS 512
#define SCAN_NB ((NN + SCAN_BS - 1) / SCAN_BS)   // 196

// ---------------- scratch (device globals; no runtime allocation) ----------
__device__ __half    g_hh[(size_t)NN * FH];   // dinv-prescaled GEMM output (25.6MB)
__device__ __half    g_th[(size_t)NN * FH];   // layer-1 output t (25.6MB)
__device__ int       g_deg[NN];
__device__ float     g_dinv[NN];
__device__ int       g_off[NN + 1];
__device__ int       g_cur[NN];
__device__ int       g_esrc[NE];
__device__ int       g_bsum[SCAN_NB];
__device__ float     g_pool[NG * FH];
__device__ int       g_cnt[NG];
// W pre-packed into per-lane mma B-fragment layout:
// [wsel][pass(hi/lo) 2][kstep 8][ntile 16][lane 32][reg 2]  (uint32 = half2)
__device__ uint32_t  g_wpack[2][16384];

// ---------------- helpers ---------------------------------------------------
__device__ __forceinline__ uint32_t smem_u32(const void* p) {
    uint32_t a;
    asm("{ .reg .u64 t; cvta.to.shared.u64 t, %1; cvt.u32.u64 %0, t; }"
        : "=r"(a) : "l"(p));
    return a;
}
__device__ __forceinline__ uint32_t h2u(float a, float b) {
    __half2 h = __floats2half2_rn(a, b);
    return *(uint32_t*)&h;
}
__device__ __forceinline__ void mma16816(float* c, const uint32_t* a,
                                         uint32_t b0, uint32_t b1) {
    asm volatile(
        "mma.sync.aligned.m16n8k16.row.col.f32.f16.f16.f32 "
        "{%0,%1,%2,%3}, {%4,%5,%6,%7}, {%8,%9}, {%0,%1,%2,%3};"
        : "+f"(c[0]), "+f"(c[1]), "+f"(c[2]), "+f"(c[3])
        : "r"(a[0]), "r"(a[1]), "r"(a[2]), "r"(a[3]), "r"(b0), "r"(b1));
}

// ---------------- weight prep: fp32 W[k][n] -> packed hi/lo B fragments -----
__global__ void k_prepw(const float* __restrict__ W1, const float* __restrict__ W2) {
    int gid = blockIdx.x * blockDim.x + threadIdx.x;   // < 32768
    if (gid >= 32768) return;
    int wsel = gid >> 14;
    int rem  = gid & 16383;
    int pass = rem >> 13;
    int r2   = rem & 8191;
    int reg  = r2 & 1;
    int lane = (r2 >> 1) & 31;
    int nt   = (r2 >> 6) & 15;
    int ks   = (r2 >> 10) & 7;
    const float* W = wsel ? W2 : W1;
    int k = ks * 16 + (lane & 3) * 2 + reg * 8;
    int n = nt * 8 + (lane >> 2);
    float v0 = W[k * FH + n];
    float v1 = W[(k + 1) * FH + n];
    __half h0, h1;
    if (pass == 0) {
        h0 = __float2half_rn(v0);
        h1 = __float2half_rn(v1);
    } else {
        h0 = __float2half_rn(v0 - __half2float(__float2half_rn(v0)));
        h1 = __float2half_rn(v1 - __half2float(__float2half_rn(v1)));
    }
    __half2 p = __halves2half2(h0, h1);
    g_wpack[wsel][rem] = *(uint32_t*)&p;
}

// ---------------- small utility kernels ------------------------------------
__global__ void k_zero() {
    int i = blockIdx.x * blockDim.x + threadIdx.x;
    if (i < NN) g_deg[i] = 0;
    if (i < NG * FH) g_pool[i] = 0.f;
    if (i < NG) g_cnt[i] = 0;
}

__global__ void k_deg(const int* __restrict__ ei) {
    int e = blockIdx.x * blockDim.x + threadIdx.x;
    if (e < NE) atomicAdd(&g_deg[ei[NE + e]], 1);
}

__global__ void k_scan1() {
    __shared__ int s[SCAN_BS];
    int idx = blockIdx.x * SCAN_BS + threadIdx.x;
    int v = (idx < NN) ? g_deg[idx] : 0;
    if (idx < NN) g_dinv[idx] = rsqrtf((float)v + 1.0f);
    s[threadIdx.x] = v;
    __syncthreads();
    for (int d = 1; d < SCAN_BS; d <<= 1) {
        int t = (threadIdx.x >= d) ? s[threadIdx.x - d] : 0;
        __syncthreads();
        s[threadIdx.x] += t;
        __syncthreads();
    }
    if (idx < NN) g_off[idx + 1] = s[threadIdx.x];
    if (threadIdx.x == SCAN_BS - 1) g_bsum[blockIdx.x] = s[SCAN_BS - 1];
}

__global__ void k_scan2() {
    __shared__ int s[256];
    int v = (threadIdx.x < SCAN_NB) ? g_bsum[threadIdx.x] : 0;
    s[threadIdx.x] = v;
    __syncthreads();
    for (int d = 1; d < 256; d <<= 1) {
        int t = (threadIdx.x >= d) ? s[threadIdx.x - d] : 0;
        __syncthreads();
        s[threadIdx.x] += t;
        __syncthreads();
    }
    if (threadIdx.x < SCAN_NB) g_bsum[threadIdx.x] = s[threadIdx.x];
}

__global__ void k_scan3() {
    int idx = blockIdx.x * SCAN_BS + threadIdx.x;
    int base = (blockIdx.x == 0) ? 0 : g_bsum[blockIdx.x - 1];
    if (idx < NN) {
        int v = g_off[idx + 1] + base;
        g_off[idx + 1] = v;
        if (idx + 1 < NN) g_cur[idx + 1] = v;
    }
    if (idx == 0) { g_off[0] = 0; g_cur[0] = 0; }
}

__global__ void k_fill(const int* __restrict__ ei) {
    int e = blockIdx.x * blockDim.x + threadIdx.x;
    if (e < NE) {
        int src = ei[e];
        int dst = ei[NE + e];
        int p = atomicAdd(&g_cur[dst], 1);
        g_esrc[p] = src;
    }
}

// ---------------- mma.sync GEMM: Y = dinv .* (X @ (Wh + Wl)) as fp16 --------
// CTA: 128 rows x 128 cols, 8 warps (4x2), warp tile m32 x n64.
// smem: Xs 32KB (swizzled fp16) + W pack 64KB = 96KB.
#define GEMM_SMEM (32768 + 65536)
__global__ void __launch_bounds__(256, 2)
k_gemm(const float* __restrict__ Xf, const __half* __restrict__ Xh,
       int wsel, __half* __restrict__ Y, int nrows) {
    extern __shared__ char sm[];
    char* Xs = sm;                               // [128 rows][16 chunks of 16B], swizzled
    uint32_t* Wsm = (uint32_t*)(sm + 32768);     // 16384 u32
    int tid = threadIdx.x, wid = tid >> 5, lane = tid & 31;
    int row0 = blockIdx.x * 128;

    // copy packed W (both passes, 64KB)
    {
        const uint4* src = (const uint4*)g_wpack[wsel];
        uint4* dst = (uint4*)Wsm;
#pragma unroll
        for (int i = 0; i < 16; i++) dst[tid + 256 * i] = src[tid + 256 * i];
    }
    // fill Xs: row r, chunk c (8 fp16 = 16B); phys chunk = c ^ (r&7)
    if (Xf) {
        const float4* X4 = (const float4*)Xf;
#pragma unroll
        for (int it = 0; it < 8; it++) {
            int g = tid + 256 * it;
            int r = g >> 4, c = g & 15;
            uint4 o = make_uint4(0, 0, 0, 0);
            if (row0 + r < nrows) {
                float4 a = X4[(size_t)(row0 + r) * 32 + c * 2];
                float4 b = X4[(size_t)(row0 + r) * 32 + c * 2 + 1];
                o.x = h2u(a.x, a.y); o.y = h2u(a.z, a.w);
                o.z = h2u(b.x, b.y); o.w = h2u(b.z, b.w);
            }
            *(uint4*)(Xs + r * 256 + ((c ^ (r & 7)) * 16)) = o;
        }
    } else {
        const uint4* X4 = (const uint4*)Xh;
#pragma unroll
        for (int it = 0; it < 8; it++) {
            int g = tid + 256 * it;
            int r = g >> 4, c = g & 15;
            uint4 o = make_uint4(0, 0, 0, 0);
            if (row0 + r < nrows) o = X4[(size_t)(row0 + r) * 16 + c];
            *(uint4*)(Xs + r * 256 + ((c ^ (r & 7)) * 16)) = o;
        }
    }
    __syncthreads();

    int wr = wid & 3;        // row group: rows 32*wr .. 32*wr+31
    int wc = wid >> 2;       // col group: cols 64*wc .. 64*wc+63
    float acc[2][8][4];
#pragma unroll
    for (int mt = 0; mt < 2; mt++)
#pragma unroll
        for (int nt = 0; nt < 8; nt++)
#pragma unroll
            for (int q = 0; q < 4; q++) acc[mt][nt][q] = 0.f;

    uint32_t smx = smem_u32(Xs);
    const uint2* W2v = (const uint2*)Wsm;   // [pass*4096 + (ks*16+ntg)*32 + lane]

#pragma unroll
    for (int ks = 0; ks < 8; ks++) {
        uint32_t a[2][4];
#pragma unroll
        for (int mt = 0; mt < 2; mt++) {
            int sub = lane >> 3;                       // 0..3
            int r = 32 * wr + 16 * mt + (lane & 7) + (sub & 1) * 8;
            int c = ks * 2 + (sub >> 1);
            uint32_t addr = smx + r * 256 + ((c ^ (r & 7)) * 16);
            asm volatile(
                "ldmatrix.sync.aligned.m8n8.x4.shared.b16 {%0,%1,%2,%3}, [%4];"
                : "=r"(a[mt][0]), "=r"(a[mt][1]), "=r"(a[mt][2]), "=r"(a[mt][3])
                : "r"(addr));
        }
#pragma unroll
        for (int nt = 0; nt < 8; nt++) {
            int ntg = 8 * wc + nt;
            uint2 bh = W2v[(ks * 16 + ntg) * 32 + lane];
            uint2 bl = W2v[4096 + (ks * 16 + ntg) * 32 + lane];
            mma16816(acc[0][nt], a[0], bh.x, bh.y);
            mma16816(acc[1][nt], a[1], bh.x, bh.y);
            mma16816(acc[0][nt], a[0], bl.x, bl.y);
            mma16816(acc[1][nt], a[1], bl.x, bl.y);
        }
    }

    // epilogue: scale by dinv[row], store fp16
#pragma unroll
    for (int mt = 0; mt < 2; mt++) {
        int r0 = row0 + 32 * wr + 16 * mt + (lane >> 2);
        int r1 = r0 + 8;
        float s0 = (r0 < nrows) ? g_dinv[r0] : 0.f;
        float s1 = (r1 < nrows) ? g_dinv[r1] : 0.f;
#pragma unroll
        for (int nt = 0; nt < 8; nt++) {
            int col = 64 * wc + 8 * nt + (lane & 3) * 2;
            if (r0 < nrows)
                *(uint32_t*)&Y[(size_t)r0 * FH + col] =
                    h2u(acc[mt][nt][0] * s0, acc[mt][nt][1] * s0);
            if (r1 < nrows)
                *(uint32_t*)&Y[(size_t)r1 * FH + col] =
                    h2u(acc[mt][nt][2] * s1, acc[mt][nt][3] * s1);
        }
    }
}

// ---------------- aggregation: one warp per dst node, fp16 gather -----------
// H holds h' = dinv .* (X@W). out = relu(dinv[d]*(sum_src h'[src] + h'[d]) + b)
__global__ void k_agg(const __half* __restrict__ H, const float* __restrict__ bias,
                      const int* __restrict__ batch, __half* __restrict__ OutH,
                      int do_pool) {
    int node = (blockIdx.x * blockDim.x + threadIdx.x) >> 5;
    int lane = threadIdx.x & 31;
    if (node >= NN) return;
    int s = g_off[node];
    int e = g_off[node + 1];
    const uint2* H2 = (const uint2*)H;    // 4 halves per lane, 32 lanes = 128
    float a0 = 0.f, a1 = 0.f, a2 = 0.f, a3 = 0.f;
#pragma unroll 4
    for (int j = s; j < e; j++) {
        int src = __ldg(&g_esrc[j]);
        uint2 v = __ldg(&H2[(size_t)src * 32 + lane]);
        float2 f0 = __half22float2(*(__half2*)&v.x);
        float2 f1 = __half22float2(*(__half2*)&v.y);
        a0 += f0.x; a1 += f0.y; a2 += f1.x; a3 += f1.y;
    }
    {   // self term
        uint2 v = __ldg(&H2[(size_t)node * 32 + lane]);
        float2 f0 = __half22float2(*(__half2*)&v.x);
        float2 f1 = __half22float2(*(__half2*)&v.y);
        a0 += f0.x; a1 += f0.y; a2 += f1.x; a3 += f1.y;
    }
    float di = g_dinv[node];
    float4 bv = __ldg(&((const float4*)bias)[lane]);
    float r0 = fmaxf(di * a0 + bv.x, 0.f);
    float r1 = fmaxf(di * a1 + bv.y, 0.f);
    float r2 = fmaxf(di * a2 + bv.z, 0.f);
    float r3 = fmaxf(di * a3 + bv.w, 0.f);
    if (OutH) {
        uint2 o;
        o.x = h2u(r0, r1);
        o.y = h2u(r2, r3);
        ((uint2*)OutH)[(size_t)node * 32 + lane] = o;
    }
    if (do_pool) {
        int b = __ldg(&batch[node]);
        float* p = &g_pool[b * FH + lane * 4];
        atomicAdd(p + 0, r0);
        atomicAdd(p + 1, r1);
        atomicAdd(p + 2, r2);
        atomicAdd(p + 3, r3);
        if (lane == 0) atomicAdd(&g_cnt[b], 1);
    }
}

// ---------------- final MLP head: one block per graph -----------------------
__global__ void k_mlp(const float* __restrict__ Wl1, const float* __restrict__ bl1,
                      const float* __restrict__ Wl2, const float* __restrict__ bl2,
                      float* __restrict__ out) {
    __shared__ float gv[FH];
    __shared__ float tv[FH];
    int b = blockIdx.x, tid = threadIdx.x;
    float c = fmaxf((float)g_cnt[b], 1.0f);
    gv[tid] = g_pool[b * FH + tid] / c;
    __syncthreads();
    float s = bl1[tid];
#pragma unroll 8
    for (int k = 0; k < FH; k++) s += gv[k] * Wl1[k * FH + tid];
    tv[tid] = fmaxf(s, 0.f);
    __syncthreads();
    if (tid < NA) {
        float o = bl2[tid];
#pragma unroll 8
        for (int k = 0; k < FH; k++) o += tv[k] * Wl2[k * NA + tid];
        out[b * NA + tid] = o;
    }
}

// ---------------- launch ----------------------------------------------------
extern "C" void kernel_launch(void* const* d_in, const int* in_sizes, int n_in,
                              void* d_out, int out_size) {
    const float* x   = (const float*)d_in[0];
    const int*   ei  = (const int*)d_in[1];
    const int*   bat = (const int*)d_in[2];
    const float* W1  = (const float*)d_in[3];
    const float* b1  = (const float*)d_in[4];
    const float* W2  = (const float*)d_in[5];
    const float* b2  = (const float*)d_in[6];
    const float* Wl1 = (const float*)d_in[7];
    const float* bl1 = (const float*)d_in[8];
    const float* Wl2 = (const float*)d_in[9];
    const float* bl2 = (const float*)d_in[10];
    float* out = (float*)d_out;

    __half *phh = nullptr, *pth = nullptr;
    cudaGetSymbolAddress((void**)&phh, g_hh);
    cudaGetSymbolAddress((void**)&pth, g_th);

    cudaFuncSetAttribute(k_gemm, cudaFuncAttributeMaxDynamicSharedMemorySize,
                         GEMM_SMEM);

    const int GB = (NN + 127) / 128;   // 782

    k_prepw<<<128, 256>>>(W1, W2);                                   // 1
    k_zero<<<(NN + 255) / 256, 256>>>();                             // 2
    k_deg<<<(NE + 255) / 256, 256>>>(ei);                            // 3
    k_scan1<<<SCAN_NB, SCAN_BS>>>();                                 // 4 (+dinv)
    k_scan2<<<1, 256>>>();                                           // 5
    k_gemm<<<GB, 256, GEMM_SMEM>>>(x, nullptr, 0, phh, NN);          // 6 (profiled)
    k_scan3<<<SCAN_NB, SCAN_BS>>>();                                 // 7 (+cur)
    k_fill<<<(NE + 255) / 256, 256>>>(ei);                           // 8
    k_agg<<<(NN * 32 + 255) / 256, 256>>>(phh, b1, bat, pth, 0);     // 9
    k_gemm<<<GB, 256, GEMM_SMEM>>>(nullptr, pth, 1, phh, NN);        // 10
    k_agg<<<(NN * 32 + 255) / 256, 256>>>(phh, b2, bat, nullptr, 1); // 11
    k_mlp<<<NG, FH>>>(Wl1, bl1, Wl2, bl2, out);                      // 12
}